// round 1
// baseline (speedup 1.0000x reference)
#include <cuda_runtime.h>
#include <math.h>

#define L_SEQ 1024
#define DM 768
#define DI 1536
#define DSTATE 16
#define DCONV 4
#define DTRANK 48
#define NLAYER 4
#define VOCAB 50280
#define DBL_W (DTRANK + 2*DSTATE)   // 80

// ---------------- scratch (device globals: no allocation allowed) ----------
__device__ float g_h [L_SEQ*DM];
__device__ float g_hn[L_SEQ*DM];
__device__ float g_xz[L_SEQ*2*DI];
__device__ float g_xc[L_SEQ*DI];
__device__ float g_dbl[L_SEQ*DBL_W];
__device__ float g_dt[L_SEQ*DI];
__device__ float g_y [L_SEQ*DI];

// ---------------- embedding gather ----------------------------------------
__global__ void embed_kernel(const int* __restrict__ ids,
                             const float* __restrict__ emb)
{
    int l = blockIdx.x;
    int id = ids[l];
    const float4* src = (const float4*)(emb + (size_t)id * DM);
    float4* dst = (float4*)(g_h + (size_t)l * DM);
    dst[threadIdx.x] = src[threadIdx.x];   // 192 threads * float4 = 768
}

// ---------------- rmsnorm --------------------------------------------------
__global__ void rmsnorm_kernel(const float* __restrict__ in,
                               float* __restrict__ out,
                               const float* __restrict__ w)
{
    int l = blockIdx.x;
    const float* x = in + (size_t)l * DM;
    float ss = 0.f;
    for (int i = threadIdx.x; i < DM; i += 256) {
        float v = x[i];
        ss = fmaf(v, v, ss);
    }
    #pragma unroll
    for (int off = 16; off >= 1; off >>= 1)
        ss += __shfl_xor_sync(0xffffffffu, ss, off);

    __shared__ float red[8];
    __shared__ float scale_s;
    int warp = threadIdx.x >> 5, lane = threadIdx.x & 31;
    if (lane == 0) red[warp] = ss;
    __syncthreads();
    if (threadIdx.x == 0) {
        float t = 0.f;
        #pragma unroll
        for (int i = 0; i < 8; i++) t += red[i];
        scale_s = rsqrtf(t / (float)DM + 1e-5f);
    }
    __syncthreads();
    float scale = scale_s;
    for (int i = threadIdx.x; i < DM; i += 256)
        out[(size_t)l * DM + i] = x[i] * scale * w[i];
}

// ---------------- depthwise causal conv (k=4) + bias + silu ----------------
__global__ void conv_silu_kernel(const float* __restrict__ cw,
                                 const float* __restrict__ cb)
{
    int idx = blockIdx.x * blockDim.x + threadIdx.x;   // < L_SEQ*DI
    int l = idx / DI;
    int d = idx - l * DI;
    float4 wv = *(const float4*)(cw + (size_t)d * 4);
    float acc = cb[d];
    const float* wj = (const float*)&wv;
    #pragma unroll
    for (int j = 0; j < DCONV; j++) {
        int ll = l - (DCONV - 1) + j;
        if (ll >= 0) acc = fmaf(wj[j], g_xz[(size_t)ll * 2 * DI + d], acc);
    }
    // silu
    acc = acc / (1.f + __expf(-acc));
    g_xc[idx] = acc;
}

// ---------------- selective scan: 2 channels per warp, 16 state-lanes each -
__global__ void scan_kernel(const float* __restrict__ A_log)
{
    int gw   = (blockIdx.x * blockDim.x + threadIdx.x) >> 5; // global warp
    int lane = threadIdx.x & 31;
    int n    = lane & 15;            // state index
    int ch   = gw * 2 + (lane >> 4); // channel 0..1535

    float Aval = -__expf(A_log[(size_t)ch * DSTATE + n]);
    float s = 0.f;
    for (int l = 0; l < L_SEQ; l++) {
        float dtv = g_dt [(size_t)l * DI + ch];
        float xcv = g_xc [(size_t)l * DI + ch];
        float Bv  = g_dbl[(size_t)l * DBL_W + DTRANK + n];
        float Cv  = g_dbl[(size_t)l * DBL_W + DTRANK + DSTATE + n];
        s = __expf(dtv * Aval) * s + dtv * Bv * xcv;   // loop-carried chain
        float p = s * Cv;                               // reduction off-path
        p += __shfl_xor_sync(0xffffffffu, p, 1);
        p += __shfl_xor_sync(0xffffffffu, p, 2);
        p += __shfl_xor_sync(0xffffffffu, p, 4);
        p += __shfl_xor_sync(0xffffffffu, p, 8);
        if (n == 0) g_y[(size_t)l * DI + ch] = p;
    }
}

// ---------------- y = (y + xc*D) * silu(z) ---------------------------------
__global__ void y_epi_kernel(const float* __restrict__ Dp)
{
    int idx = blockIdx.x * blockDim.x + threadIdx.x;   // < L_SEQ*DI
    int l = idx / DI;
    int d = idx - l * DI;
    float z  = g_xz[(size_t)l * 2 * DI + DI + d];
    float yv = g_y[idx] + g_xc[idx] * Dp[d];
    yv *= z / (1.f + __expf(-z));
    g_y[idx] = yv;
}

// ---------------- generic TN GEMM: C[m][n] = sum_k A[m][k]*B[n][k] ---------
// BM=128 BN=64 BK=16, 256 threads, 8x4 microtile.
// EPI: 0 = store, 1 = softplus(acc + bias[n]) store, 2 = C += acc (residual)
#define GBM 128
#define GBN 64
#define GBK 16

template<int EPI>
__global__ __launch_bounds__(256)
void gemm_tn(const float* __restrict__ A, int lda,
             const float* __restrict__ B, int ldb,
             float* __restrict__ C, int ldc,
             int N, int K, const float* __restrict__ bias)
{
    __shared__ float As[GBK][GBM + 4];
    __shared__ float Bs[GBK][GBN + 4];

    const int bm  = blockIdx.y * GBM;
    const int bn  = blockIdx.x * GBN;
    const int tid = threadIdx.x;
    const int tx  = tid & 15;   // n direction
    const int ty  = tid >> 4;   // m direction
    const int a_row = tid >> 1;          // 0..127
    const int a_k   = (tid & 1) * 8;     // 0 or 8
    const int b_row = tid >> 2;          // 0..63
    const int b_k   = (tid & 3) * 4;     // 0,4,8,12

    float acc[8][4];
    #pragma unroll
    for (int i = 0; i < 8; i++)
        #pragma unroll
        for (int j = 0; j < 4; j++) acc[i][j] = 0.f;

    const float* Aptr = A + (size_t)(bm + a_row) * lda + a_k;
    const int gbn = bn + b_row;
    const float* Bptr = (gbn < N) ? (B + (size_t)gbn * ldb + b_k) : 0;

    for (int k0 = 0; k0 < K; k0 += GBK) {
        float4 av0 = *(const float4*)(Aptr + k0);
        float4 av1 = *(const float4*)(Aptr + k0 + 4);
        float4 bv  = Bptr ? *(const float4*)(Bptr + k0)
                          : make_float4(0.f, 0.f, 0.f, 0.f);

        As[a_k + 0][a_row] = av0.x; As[a_k + 1][a_row] = av0.y;
        As[a_k + 2][a_row] = av0.z; As[a_k + 3][a_row] = av0.w;
        As[a_k + 4][a_row] = av1.x; As[a_k + 5][a_row] = av1.y;
        As[a_k + 6][a_row] = av1.z; As[a_k + 7][a_row] = av1.w;
        Bs[b_k + 0][b_row] = bv.x;  Bs[b_k + 1][b_row] = bv.y;
        Bs[b_k + 2][b_row] = bv.z;  Bs[b_k + 3][b_row] = bv.w;
        __syncthreads();

        #pragma unroll
        for (int kk = 0; kk < GBK; kk++) {
            float ar[8], br[4];
            #pragma unroll
            for (int i = 0; i < 8; i++) ar[i] = As[kk][ty * 8 + i];
            #pragma unroll
            for (int j = 0; j < 4; j++) br[j] = Bs[kk][tx * 4 + j];
            #pragma unroll
            for (int i = 0; i < 8; i++)
                #pragma unroll
                for (int j = 0; j < 4; j++)
                    acc[i][j] = fmaf(ar[i], br[j], acc[i][j]);
        }
        __syncthreads();
    }

    #pragma unroll
    for (int i = 0; i < 8; i++) {
        int m = bm + ty * 8 + i;
        #pragma unroll
        for (int j = 0; j < 4; j++) {
            int n = bn + tx * 4 + j;
            if (n < N) {
                float v = acc[i][j];
                if (EPI == 1) {
                    v += bias[n];
                    // numerically stable softplus = max(x,0)+log1p(exp(-|x|))
                    v = fmaxf(v, 0.f) + log1pf(__expf(-fabsf(v)));
                }
                if (EPI == 2) C[(size_t)m * ldc + n] += v;
                else          C[(size_t)m * ldc + n] = v;
            }
        }
    }
}

// ---------------- orchestration --------------------------------------------
extern "C" void kernel_launch(void* const* d_in, const int* in_sizes, int n_in,
                              void* d_out, int out_size)
{
    const int*   ids        = (const int*)  d_in[0];
    const float* emb        = (const float*)d_in[1];
    const float* in_proj_w  = (const float*)d_in[2];
    const float* conv_w     = (const float*)d_in[3];
    const float* conv_b     = (const float*)d_in[4];
    const float* x_proj_w   = (const float*)d_in[5];
    const float* dt_proj_w  = (const float*)d_in[6];
    const float* dt_proj_b  = (const float*)d_in[7];
    const float* A_log      = (const float*)d_in[8];
    const float* D_param    = (const float*)d_in[9];
    const float* out_proj_w = (const float*)d_in[10];
    const float* norm_w     = (const float*)d_in[11];
    const float* norm_f_w   = (const float*)d_in[12];
    float* logits = (float*)d_out;

    float *h, *hn, *xz, *xc, *dbl, *dt, *y;
    cudaGetSymbolAddress((void**)&h,   g_h);
    cudaGetSymbolAddress((void**)&hn,  g_hn);
    cudaGetSymbolAddress((void**)&xz,  g_xz);
    cudaGetSymbolAddress((void**)&xc,  g_xc);
    cudaGetSymbolAddress((void**)&dbl, g_dbl);
    cudaGetSymbolAddress((void**)&dt,  g_dt);
    cudaGetSymbolAddress((void**)&y,   g_y);

    embed_kernel<<<L_SEQ, DM / 4>>>(ids, emb);

    for (int i = 0; i < NLAYER; i++) {
        rmsnorm_kernel<<<L_SEQ, 256>>>(h, hn, norm_w + (size_t)i * DM);

        // xz = hn @ in_proj_w^T   (1024 x 3072, K=768)
        dim3 g1((2 * DI + GBN - 1) / GBN, L_SEQ / GBM);
        gemm_tn<0><<<g1, 256>>>(hn, DM,
                                in_proj_w + (size_t)i * 2 * DI * DM, DM,
                                xz, 2 * DI, 2 * DI, DM, 0);

        // xc = silu(conv(x) + b)
        conv_silu_kernel<<<(L_SEQ * DI) / 256, 256>>>(
            conv_w + (size_t)i * DI * DCONV, conv_b + (size_t)i * DI);

        // dbl = xc @ x_proj_w^T   (1024 x 80, K=1536)
        dim3 g2((DBL_W + GBN - 1) / GBN, L_SEQ / GBM);
        gemm_tn<0><<<g2, 256>>>(xc, DI,
                                x_proj_w + (size_t)i * DBL_W * DI, DI,
                                dbl, DBL_W, DBL_W, DI, 0);

        // dt = softplus(dbl[:, :48] @ dt_proj_w^T + dt_b)  (1024 x 1536, K=48)
        dim3 g3((DI + GBN - 1) / GBN, L_SEQ / GBM);
        gemm_tn<1><<<g3, 256>>>(dbl, DBL_W,
                                dt_proj_w + (size_t)i * DI * DTRANK, DTRANK,
                                dt, DI, DI, DTRANK,
                                dt_proj_b + (size_t)i * DI);

        // selective scan (sequential over L)
        scan_kernel<<<DI / 8, 128>>>(A_log + (size_t)i * DI * DSTATE);

        // y = (y + xc*D) * silu(z)
        y_epi_kernel<<<(L_SEQ * DI) / 256, 256>>>(D_param + (size_t)i * DI);

        // h += y @ out_proj_w^T   (1024 x 768, K=1536), residual accumulate
        dim3 g4((DM + GBN - 1) / GBN, L_SEQ / GBM);
        gemm_tn<2><<<g4, 256>>>(y, DI,
                                out_proj_w + (size_t)i * DM * DI, DI,
                                h, DM, DM, DI, 0);
    }

    rmsnorm_kernel<<<L_SEQ, 256>>>(h, hn, norm_f_w);

    // logits = hn @ emb^T   (1024 x 50280, K=768) — the dominant GEMM
    dim3 g5((VOCAB + GBN - 1) / GBN, L_SEQ / GBM);
    gemm_tn<0><<<g5, 256>>>(hn, DM, emb, DM, logits, VOCAB, VOCAB, DM, 0);
}